// round 1
// baseline (speedup 1.0000x reference)
#include <cuda_runtime.h>
#include <cuda_bf16.h>
#include <math.h>

// NT-Xent loss, fused. B=4096, D=128, N=8192 (shapes derived from in_sizes).
//   loss = mean_i [ -sim(i, pos(i)) + log(sum_{j != i} exp(sim(i,j))) ]
//   sim(i,j) = (zn_i . zn_j) / 0.5,  zn = row-l2-normalized concat(z_i, z_j)
//
// Pipeline:
//   K1 normalize  : z_i,z_j -> g_zn [N,128] fp32
//   K2 simloss    : tiled 128x128 fp32 GEMM-like pass, per-row sumexp + pos logit
//                   (column-split CS=4, partial results, no atomics)
//   K3 finalize   : combine partials, mean -> d_out[0]

#define D_DIM   128
#define N_MAX   8192
#define BM      128
#define BN      128
#define TM      8
#define TN      8
#define CS      4
#define LDA     132              // 128 + 4 pad: keeps float4 alignment, 4-way store conflict only
#define TEMP_INV 2.0f            // 1 / 0.5

__device__ float g_zn[N_MAX * D_DIM];
__device__ float g_sumexp[CS * N_MAX];
__device__ float g_pos[CS * N_MAX];

// ---------------------------------------------------------------- K1: normalize
__global__ void ntx_normalize(const float* __restrict__ zi,
                              const float* __restrict__ zj, int Bv) {
    int warp = (blockIdx.x * blockDim.x + threadIdx.x) >> 5;
    int lane = threadIdx.x & 31;
    int Nv = 2 * Bv;
    if (warp >= Nv) return;
    const float* src = (warp < Bv) ? (zi + (size_t)warp * D_DIM)
                                   : (zj + (size_t)(warp - Bv) * D_DIM);
    float v[4];
    float ss = 0.f;
#pragma unroll
    for (int i = 0; i < 4; i++) {
        v[i] = src[lane + 32 * i];
        ss += v[i] * v[i];
    }
#pragma unroll
    for (int o = 16; o; o >>= 1) ss += __shfl_xor_sync(0xFFFFFFFFu, ss, o);
    float rn = 1.0f / fmaxf(sqrtf(ss), 1e-12f);
#pragma unroll
    for (int i = 0; i < 4; i++)
        g_zn[(size_t)warp * D_DIM + lane + 32 * i] = v[i] * rn;
}

// ---------------------------------------------------------------- K2: sim + lse partials
__global__ __launch_bounds__(256, 1)
void ntx_simloss(int Bv) {
    extern __shared__ float sm[];
    float* As = sm;                 // [128][LDA] k-major: As[k*LDA + r]
    float* Bs = sm + D_DIM * LDA;   // [128][LDA] k-major

    const int Nv = 2 * Bv;
    const int bid = blockIdx.x;
    const int rowGroup = bid / CS;
    const int cs = bid % CS;
    const int rowStart = rowGroup * BM;
    const int colsPerChunk = Nv / CS;
    const int colStart = cs * colsPerChunk;

    const int t  = threadIdx.x;
    const int tx = t & 15;
    const int ty = t >> 4;

    // Load A tile (rows rowStart..+127) transposed into smem (once per block).
#pragma unroll
    for (int i = 0; i < (BM * D_DIM) / 256; i++) {
        int idx = t + i * 256;
        int r = idx >> 7;           // / 128
        int k = idx & 127;
        As[k * LDA + r] = g_zn[(size_t)(rowStart + r) * D_DIM + k];
    }

    float sumexp[TM], pos[TM];
#pragma unroll
    for (int i = 0; i < TM; i++) { sumexp[i] = 0.f; pos[i] = 0.f; }

    for (int ct = 0; ct < colsPerChunk / BN; ct++) {
        const int colBase = colStart + ct * BN;

        __syncthreads();            // previous tile's compute done (also covers A stores on first iter)
#pragma unroll
        for (int i = 0; i < (BN * D_DIM) / 256; i++) {
            int idx = t + i * 256;
            int r = idx >> 7;
            int k = idx & 127;
            Bs[k * LDA + r] = g_zn[(size_t)(colBase + r) * D_DIM + k];
        }
        __syncthreads();

        float acc[TM][TN];
#pragma unroll
        for (int i = 0; i < TM; i++)
#pragma unroll
            for (int j = 0; j < TN; j++) acc[i][j] = 0.f;

#pragma unroll 4
        for (int k = 0; k < D_DIM; ++k) {
            const float* ap = &As[k * LDA + ty * TM];
            const float* bp = &Bs[k * LDA + tx * TN];
            float4 a0 = *(const float4*)(ap);
            float4 a1 = *(const float4*)(ap + 4);
            float4 b0 = *(const float4*)(bp);
            float4 b1 = *(const float4*)(bp + 4);
            float a[8] = {a0.x, a0.y, a0.z, a0.w, a1.x, a1.y, a1.z, a1.w};
            float b[8] = {b0.x, b0.y, b0.z, b0.w, b1.x, b1.y, b1.z, b1.w};
#pragma unroll
            for (int i = 0; i < TM; i++)
#pragma unroll
                for (int j = 0; j < TN; j++)
                    acc[i][j] = fmaf(a[i], b[j], acc[i][j]);
        }

        // epilogue: exp + diag exclusion + positive-pair pick
#pragma unroll
        for (int i = 0; i < TM; i++) {
            int r = rowStart + ty * TM + i;
            int cpos = r + Bv; if (cpos >= Nv) cpos -= Nv;   // (r+B) % N
#pragma unroll
            for (int j = 0; j < TN; j++) {
                int c = colBase + tx * TN + j;
                float s = acc[i][j] * TEMP_INV;
                float e = __expf(s);
                sumexp[i] += (r == c) ? 0.f : e;
                if (c == cpos) pos[i] += s;
            }
        }
    }

    // Reduce across the 16 tx lanes that share each row (half-warp xor shuffles).
#pragma unroll
    for (int i = 0; i < TM; i++) {
        float se = sumexp[i], p = pos[i];
#pragma unroll
        for (int o = 8; o; o >>= 1) {
            se += __shfl_xor_sync(0xFFFFFFFFu, se, o);
            p  += __shfl_xor_sync(0xFFFFFFFFu, p,  o);
        }
        if (tx == 0) {
            int r = rowStart + ty * TM + i;
            g_sumexp[cs * Nv + r] = se;
            g_pos[cs * Nv + r]    = p;
        }
    }
}

// ---------------------------------------------------------------- K3: finalize (mean)
__global__ void ntx_finalize(float* __restrict__ out, int Bv) {
    const int Nv = 2 * Bv;
    __shared__ float red[256];
    float acc = 0.f;
    for (int r = threadIdx.x; r < Nv; r += blockDim.x) {
        float se = 0.f, p = 0.f;
#pragma unroll
        for (int c = 0; c < CS; c++) {
            se += g_sumexp[c * Nv + r];
            p  += g_pos[c * Nv + r];
        }
        acc += (logf(se) - p);
    }
    red[threadIdx.x] = acc;
    __syncthreads();
    for (int s = 128; s > 0; s >>= 1) {
        if (threadIdx.x < s) red[threadIdx.x] += red[threadIdx.x + s];
        __syncthreads();
    }
    if (threadIdx.x == 0) out[0] = red[0] / (float)Nv;
}

// ---------------------------------------------------------------- launch
extern "C" void kernel_launch(void* const* d_in, const int* in_sizes, int n_in,
                              void* d_out, int out_size) {
    const float* zi = (const float*)d_in[0];
    const float* zj = (const float*)d_in[1];
    const int Bv = in_sizes[0] / D_DIM;   // 4096
    const int Nv = 2 * Bv;                // 8192

    const int smem = 2 * D_DIM * LDA * (int)sizeof(float);  // 135168 B
    cudaFuncSetAttribute(ntx_simloss, cudaFuncAttributeMaxDynamicSharedMemorySize, smem);

    // K1: one warp per row, 8 warps / block
    ntx_normalize<<<Nv / 8, 256>>>(zi, zj, Bv);
    // K2: 64 row-groups x 4 column chunks = 256 blocks
    ntx_simloss<<<(Nv / BM) * CS, 256, smem>>>(Bv);
    // K3
    ntx_finalize<<<1, 256>>>((float*)d_out, Bv);
}

// round 7
// speedup vs baseline: 4.5918x; 4.5918x over previous
#include <cuda_runtime.h>
#include <cuda_bf16.h>
#include <math.h>
#include <cstdint>

// NT-Xent loss via mma.sync bf16 HMMA (plain sm_103-target PTX; tcgen05 is
// rejected by this harness's compute_103 PTX stage).
//   K1 normalize: z_i,z_j -> g_znh [N,128] bf16 row-l2-normalized
//   K2 simloss  : 128-row block x 4096-col chunk per CTA; bf16 m16n8k16 MMA,
//                 fp32 accum, fused exp+reduce epilogue. cp.async double-buffered
//                 B tiles, XOR-swizzled smem, conflict-free ldmatrix.
//   K3 finalize : combine CS partials, mean -> d_out[0]

#define D_DIM     128
#define N_MAX     8192
#define CS        2
#define LOG2E_X2  2.885390081777927f   // 2 * log2(e)  (folds /T into exp2)

__device__ __nv_bfloat16 g_znh[N_MAX * D_DIM];
__device__ float g_sumexp[CS * N_MAX];
__device__ float g_pos[CS * N_MAX];

// ------------------------------------------------------------- helpers
__device__ __forceinline__ uint32_t smem_u32(const void* p) {
    uint32_t a;
    asm("{ .reg .u64 t; cvta.to.shared.u64 t, %1; cvt.u32.u64 %0, t; }" : "=r"(a) : "l"(p));
    return a;
}
__device__ __forceinline__ void cp_async16(uint32_t saddr, const void* gaddr) {
    asm volatile("cp.async.cg.shared.global [%0], [%1], 16;" :: "r"(saddr), "l"(gaddr));
}
#define CP_COMMIT() asm volatile("cp.async.commit_group;" ::: "memory")
#define CP_WAIT(n)  asm volatile("cp.async.wait_group %0;" :: "n"(n) : "memory")

__device__ __forceinline__ void ldsm_x4(uint32_t* r, uint32_t addr) {
    asm volatile("ldmatrix.sync.aligned.m8n8.x4.shared.b16 {%0,%1,%2,%3}, [%4];"
                 : "=r"(r[0]), "=r"(r[1]), "=r"(r[2]), "=r"(r[3]) : "r"(addr));
}
__device__ __forceinline__ void mma16816(float* d, const uint32_t* a, const uint32_t* b) {
    asm volatile(
        "mma.sync.aligned.m16n8k16.row.col.f32.bf16.bf16.f32 "
        "{%0,%1,%2,%3}, {%4,%5,%6,%7}, {%8,%9}, {%0,%1,%2,%3};"
        : "+f"(d[0]), "+f"(d[1]), "+f"(d[2]), "+f"(d[3])
        : "r"(a[0]), "r"(a[1]), "r"(a[2]), "r"(a[3]), "r"(b[0]), "r"(b[1]));
}
__device__ __forceinline__ float ex2(float x) {
    float e;
    asm("ex2.approx.ftz.f32 %0, %1;" : "=f"(e) : "f"(x));
    return e;
}

// smem tile layout: 128 rows x 256B (128 bf16). 16B chunks, swizzle c^(row&7).
__device__ __forceinline__ uint32_t tile_addr(uint32_t base, int row, int chunk) {
    return base + row * 256 + (((uint32_t)(chunk ^ (row & 7))) << 4);
}

// ------------------------------------------------------------- K1: normalize -> bf16
__global__ void ntx_normalize(const float* __restrict__ zi,
                              const float* __restrict__ zj, int Bv) {
    int warp = (blockIdx.x * blockDim.x + threadIdx.x) >> 5;
    int lane = threadIdx.x & 31;
    int Nv = 2 * Bv;
    if (warp >= Nv) return;
    const float* src = (warp < Bv) ? (zi + (size_t)warp * D_DIM)
                                   : (zj + (size_t)(warp - Bv) * D_DIM);
    float4 v = ((const float4*)src)[lane];
    float ss = v.x * v.x + v.y * v.y + v.z * v.z + v.w * v.w;
#pragma unroll
    for (int o = 16; o; o >>= 1) ss += __shfl_xor_sync(0xFFFFFFFFu, ss, o);
    float rn = 1.0f / fmaxf(sqrtf(ss), 1e-12f);
    __nv_bfloat162 p0 = __float22bfloat162_rn(make_float2(v.x * rn, v.y * rn));
    __nv_bfloat162 p1 = __float22bfloat162_rn(make_float2(v.z * rn, v.w * rn));
    uint2 out;
    out.x = *(uint32_t*)&p0;
    out.y = *(uint32_t*)&p1;
    ((uint2*)(g_znh + (size_t)warp * D_DIM))[lane] = out;
}

// ------------------------------------------------------------- K2
#define A_OFF    0
#define B0_OFF   32768
#define B1_OFF   65536
#define RED_OFF  98304
#define SMEM_REQ 101376   // 96KB tiles + 2KB reduce + align pad

__device__ __forceinline__ void issue_tile_loads(uint32_t sdst, int srcRow, int tid) {
    int r = tid >> 1, h = tid & 1;
    const char* g = (const char*)(g_znh + (size_t)(srcRow + r) * D_DIM + h * 64);
    uint32_t srow = sdst + r * 256;
#pragma unroll
    for (int i = 0; i < 8; i++) {
        int c = h * 8 + i;
        cp_async16(srow + (((uint32_t)(c ^ (r & 7))) << 4), g + i * 16);
    }
}

__global__ __launch_bounds__(256, 1) void ntx_simloss(int Bv) {
    extern __shared__ char smraw[];
    uint32_t raw = smem_u32(smraw);
    uint32_t base = (raw + 1023u) & ~1023u;
    char* abase = smraw + (base - raw);

    const int tid = threadIdx.x, lane = tid & 31, wid = tid >> 5;
    const int Nv = 2 * Bv;
    const int rowGroup = blockIdx.x >> 1, cs = blockIdx.x & 1;
    const int rowStart = rowGroup * 128;
    const int chunkN = Nv / CS, colStart = cs * chunkN;
    const int Tiles = chunkN / 128;                    // 32

    const int wm = (wid & 3) * 32;                     // warp row offset in 128
    const int wn = (wid >> 2) * 64;                    // warp col offset in 128

    // prologue: A tile + B tile 0
    issue_tile_loads(base + A_OFF, rowStart, tid);
    issue_tile_loads(base + B0_OFF, colStart, tid);
    CP_COMMIT();

    int cpos = rowStart + Bv; if (cpos >= Nv) cpos -= Nv;
    const int diagTile = (rowStart - colStart >= 0 && rowStart - colStart < chunkN)
                             ? (rowStart - colStart) >> 7 : -1;
    const int posTile = (cpos - colStart >= 0 && cpos - colStart < chunkN)
                            ? (cpos - colStart) >> 7 : -1;

    float rAcc[2][2] = {{0.f, 0.f}, {0.f, 0.f}};       // [mt][rowhalf]
    float rPos[2][2] = {{0.f, 0.f}, {0.f, 0.f}};

    for (int ct = 0; ct < Tiles; ct++) {
        if (ct + 1 < Tiles)
            issue_tile_loads(base + (((ct + 1) & 1) ? B1_OFF : B0_OFF),
                             colStart + (ct + 1) * 128, tid);
        CP_COMMIT();
        CP_WAIT(1);                  // tile ct (and A) resident
        __syncthreads();

        const uint32_t Bb = base + ((ct & 1) ? B1_OFF : B0_OFF);

        float acc[2][8][4];
#pragma unroll
        for (int mt = 0; mt < 2; mt++)
#pragma unroll
            for (int nt = 0; nt < 8; nt++)
#pragma unroll
                for (int e = 0; e < 4; e++) acc[mt][nt][e] = 0.f;

#pragma unroll
        for (int ks = 0; ks < 8; ks++) {
            uint32_t a[2][4];
#pragma unroll
            for (int mt = 0; mt < 2; mt++) {
                int row = wm + mt * 16 + (lane & 15);
                int chunk = ks * 2 + (lane >> 4);
                ldsm_x4(a[mt], tile_addr(base + A_OFF, row, chunk));
            }
            uint32_t b[4][4];
#pragma unroll
            for (int np = 0; np < 4; np++) {
                int row = wn + (np * 2 + (lane >> 4)) * 8 + (lane & 7);
                int chunk = ks * 2 + ((lane >> 3) & 1);
                ldsm_x4(b[np], tile_addr(Bb, row, chunk));
            }
#pragma unroll
            for (int mt = 0; mt < 2; mt++)
#pragma unroll
                for (int np = 0; np < 4; np++) {
                    mma16816(acc[mt][np * 2],     a[mt], &b[np][0]);
                    mma16816(acc[mt][np * 2 + 1], a[mt], &b[np][2]);
                }
        }

        // epilogue: exp + reduce (fused /T via LOG2E_X2)
        const bool isDiag = (ct == diagTile), isPos = (ct == posTile);
        if (!isDiag && !isPos) {
#pragma unroll
            for (int mt = 0; mt < 2; mt++)
#pragma unroll
                for (int nt = 0; nt < 8; nt++) {
                    rAcc[mt][0] += ex2(acc[mt][nt][0] * LOG2E_X2)
                                 + ex2(acc[mt][nt][1] * LOG2E_X2);
                    rAcc[mt][1] += ex2(acc[mt][nt][2] * LOG2E_X2)
                                 + ex2(acc[mt][nt][3] * LOG2E_X2);
                }
        } else {
#pragma unroll
            for (int mt = 0; mt < 2; mt++) {
                int r0 = wm + mt * 16 + (lane >> 2);
                int r1 = r0 + 8;
#pragma unroll
                for (int nt = 0; nt < 8; nt++) {
                    int c0 = wn + nt * 8 + 2 * (lane & 3);
#pragma unroll
                    for (int e = 0; e < 4; e++) {
                        int r = (e < 2) ? r0 : r1;
                        int c = c0 + (e & 1);
                        float v = acc[mt][nt][e];
                        float ev = ex2(v * LOG2E_X2);
                        bool hit = (r == c);          // local diag == pos/self col
                        float* ra = &rAcc[mt][e >> 1];
                        if (isDiag) { if (!hit) *ra += ev; }
                        else { *ra += ev; if (hit) rPos[mt][e >> 1] += v * 2.0f; }
                    }
                }
            }
        }
        __syncthreads();   // all reads of Bb done before it is overwritten
    }

    // reduce across 4-lane column groups, then across the two n-warp halves
    float* rowSum = (float*)(abase + RED_OFF);        // [2][128]
    float* rowPos = rowSum + 256;                     // [2][128]
#pragma unroll
    for (int mt = 0; mt < 2; mt++)
#pragma unroll
        for (int h = 0; h < 2; h++) {
            float v = rAcc[mt][h], pv = rPos[mt][h];
            v += __shfl_xor_sync(0xFFFFFFFFu, v, 1);
            v += __shfl_xor_sync(0xFFFFFFFFu, v, 2);
            pv += __shfl_xor_sync(0xFFFFFFFFu, pv, 1);
            pv += __shfl_xor_sync(0xFFFFFFFFu, pv, 2);
            if ((lane & 3) == 0) {
                int r = wm + mt * 16 + h * 8 + (lane >> 2);
                rowSum[(wid >> 2) * 128 + r] = v;
                rowPos[(wid >> 2) * 128 + r] = pv;
            }
        }
    __syncthreads();
    if (tid < 128) {
        g_sumexp[cs * Nv + rowStart + tid] = rowSum[tid] + rowSum[128 + tid];
        g_pos[cs * Nv + rowStart + tid]    = rowPos[tid] + rowPos[128 + tid];
    }
}

// ------------------------------------------------------------- K3: finalize
__global__ void ntx_finalize(float* __restrict__ out, int Bv) {
    const int Nv = 2 * Bv;
    __shared__ float red[256];
    float acc = 0.f;
    for (int r = threadIdx.x; r < Nv; r += blockDim.x) {
        float se = 0.f, p = 0.f;
#pragma unroll
        for (int c = 0; c < CS; c++) {
            se += g_sumexp[c * Nv + r];
            p  += g_pos[c * Nv + r];
        }
        acc += (logf(se) - p);
    }
    red[threadIdx.x] = acc;
    __syncthreads();
    for (int s = 128; s > 0; s >>= 1) {
        if (threadIdx.x < s) red[threadIdx.x] += red[threadIdx.x + s];
        __syncthreads();
    }
    if (threadIdx.x == 0) out[0] = red[0] / (float)Nv;
}

// ------------------------------------------------------------- launch
extern "C" void kernel_launch(void* const* d_in, const int* in_sizes, int n_in,
                              void* d_out, int out_size) {
    const float* zi = (const float*)d_in[0];
    const float* zj = (const float*)d_in[1];
    const int Bv = in_sizes[0] / D_DIM;   // 4096
    const int Nv = 2 * Bv;                // 8192

    cudaFuncSetAttribute(ntx_simloss, cudaFuncAttributeMaxDynamicSharedMemorySize, SMEM_REQ);

    ntx_normalize<<<Nv / 8, 256>>>(zi, zj, Bv);
    ntx_simloss<<<(Nv / 128) * CS, 256, SMEM_REQ>>>(Bv);
    ntx_finalize<<<1, 256>>>((float*)d_out, Bv);
}